// round 13
// baseline (speedup 1.0000x reference)
#include <cuda_runtime.h>
#include <math.h>

#define Hh 512
#define Ww 512
#define NPIX (512*512)
#define KK 50
#define BB 16
#define SLIC_ITERS 10
#define NSLAB (SLIC_ITERS + 2)     // 12: slab it = input of assign pass it

// scratch (static device arrays; no dynamic allocation allowed)
__device__ double        g_accum[NSLAB][BB][KK][6]; // [0..4]=feat sums, [5]=count
__device__ unsigned char g_labels[BB][NPIX];
__device__ double        g_colorsum[BB][3];

__device__ __forceinline__ float ratio_f() {
    return (float)(10.0 / sqrt((double)NPIX / (double)KK));
}

// ---------------------------------------------------------------------------
// init: zero ALL accumulator slabs, seed slab 0 with {feat, cnt=1} so that
// centers0 = feat/1 exactly (grid-initialized, first 50 of 8x8 grid)
// ---------------------------------------------------------------------------
__global__ void init_kernel(const float* __restrict__ x) {
    int b = blockIdx.x;
    int tid = threadIdx.x;
    for (int i = tid; i < NSLAB * KK * 6; i += 512) {
        int slab = i / (KK * 6);
        int rem  = i - slab * (KK * 6);
        g_accum[slab][b][rem / 6][rem % 6] = 0.0;
    }
    if (b == 0 && tid >= 448 && tid < 448 + BB * 3) ((double*)g_colorsum)[tid - 448] = 0.0;
    __syncthreads();
    if (tid < KK) {
        int i = tid >> 3, j = tid & 7;
        int y = 32 + 64 * i;
        int xc = 32 + 64 * j;
        const float* xb = x + (size_t)b * 3 * NPIX;
        float r  = xb[y * Ww + xc];
        float g  = xb[NPIX + y * Ww + xc];
        float bl = xb[2 * NPIX + y * Ww + xc];
        float fr = ratio_f();
        double* a = g_accum[0][b][tid];
        a[0] = (double)r;
        a[1] = (double)g;
        a[2] = (double)bl;
        a[3] = (double)__fmul_rn((float)y, fr);
        a[4] = (double)__fmul_rn((float)xc, fr);
        a[5] = 1.0;
    }
}

// ---------------------------------------------------------------------------
// assign pass it: centers computed IN-PROLOGUE from g_accum[it] (fp32 divide,
// like JAX's sums/max(cnts,1)); segment sums atomically added to g_accum[it+1].
// Block = 64x32 tile; 1 thread = 4x2 patch; warp covers a compact 32x8 region.
// Exact spatial pruning: candidate iff smin_j <= min_j'(smax_j') + 3 [+pad].
// R13: candidates compacted in ASCENDING-smin order (rank loop), evaluated in
// fixed 8-candidate sentinel-padded rounds, with a PROVABLY-EXACT early exit:
// after a round, if for every pixel dmin_p + f2_p + PAD < smin(next slot),
// every remaining candidate satisfies d_j(p) >= smin_j - f2_p > dmin_p and
// loses under strict '<'.  (Order change only matters for bit-equal ties.)
// Reduction: warp aggregation; RGB via shfl tree, cnt/Y/X exact ints via
// REDUX; lane 0 alone issues global f64 atomics.
// ---------------------------------------------------------------------------
__global__ __launch_bounds__(256, 3) void assign_kernel(const float* __restrict__ x,
                                                        int it, int storeLabels) {
    __shared__ float4 s_candA[64];            // {-2c0,-2c1,-2c2,-2c3}
    __shared__ float2 s_candB[64];            // {-2c4, ||c||^2 or +INF sentinel}
    __shared__ unsigned char s_jidx[64];
    __shared__ float s_smax[64];
    __shared__ float s_skey[64];              // smin key (kept) or +INF
    __shared__ float s_sminS[64];             // sorted smin, +INF padded
    __shared__ unsigned int s_mask[2];
    __shared__ float s_T;

    int b   = blockIdx.y;
    int tid = threadIdx.x;
    int tileX = (blockIdx.x & 7) << 6;        // 8 x-tiles of 64
    int tileY = (blockIdx.x >> 3) << 5;       // 16 y-tiles of 32

    float fr = ratio_f();
    float byLo = __fmul_rn((float)tileY, fr);
    float byHi = __fmul_rn((float)(tileY + 31), fr);
    float bxLo = __fmul_rn((float)tileX, fr);
    float bxHi = __fmul_rn((float)(tileX + 63), fr);

    float c0 = 0.f, c1 = 0.f, c2 = 0.f, c3 = 0.f, c4 = 0.f, smin = 0.f;
    if (tid < 64) {
        s_candA[tid] = make_float4(0.f, 0.f, 0.f, 0.f);
        s_candB[tid] = make_float2(0.f, __int_as_float(0x7f800000));  // +INF
        s_jidx[tid] = 0;
        s_smax[tid] = 3.4e38f;
        s_skey[tid] = 3.4e38f;
        s_sminS[tid] = 3.4e38f;
    }
    if (tid < KK) {
        // centers from previous pass's sums (fused update, JAX-style fp32 div)
        const double* a = g_accum[it][b][tid];
        float fcnt = fmaxf((float)a[5], 1.0f);
        c0 = __fdiv_rn((float)a[0], fcnt);
        c1 = __fdiv_rn((float)a[1], fcnt);
        c2 = __fdiv_rn((float)a[2], fcnt);
        c3 = __fdiv_rn((float)a[3], fcnt);
        c4 = __fdiv_rn((float)a[4], fcnt);
        float dyo = fmaxf(fmaxf(byLo - c3, c3 - byHi), 0.0f);
        float dxo = fmaxf(fmaxf(bxLo - c4, c4 - bxHi), 0.0f);
        smin = dyo * dyo + dxo * dxo;
        float dyM = fmaxf(fabsf(c3 - byLo), fabsf(c3 - byHi));
        float dxM = fmaxf(fabsf(c4 - bxLo), fabsf(c4 - bxHi));
        s_smax[tid] = dyM * dyM + dxM * dxM;
    }
    __syncthreads();
    if (tid < 32) {                        // warp-parallel min reduction
        float v = fminf(s_smax[tid], s_smax[tid + 32]);
#pragma unroll
        for (int off = 16; off > 0; off >>= 1)
            v = fminf(v, __shfl_xor_sync(0xffffffffu, v, off));
        if (tid == 0) s_T = v + 3.0f + 1e-3f;  // color slack + fp pad
    }
    __syncthreads();
    bool keep = (tid < KK) && (smin <= s_T);
    unsigned int wm = __ballot_sync(0xffffffffu, keep);
    if (tid < 64 && (tid & 31) == 0) s_mask[tid >> 5] = wm;
    if (tid < KK) s_skey[tid] = keep ? smin : 3.4e38f;
    __syncthreads();
    unsigned int m0 = s_mask[0], m1 = s_mask[1];
    int C = __popc(m0) + __popc(m1);
    if (keep) {
        // rank by (smin, j) ascending -> compaction position
        int rank = 0;
#pragma unroll 1
        for (int k = 0; k < KK; k++) {
            float ok = s_skey[k];
            rank += (ok < smin || (ok == smin && k < tid)) ? 1 : 0;
        }
        float cc = __fmul_rn(c0, c0);
        cc = __fmaf_rn(c1, c1, cc);
        cc = __fmaf_rn(c2, c2, cc);
        cc = __fmaf_rn(c3, c3, cc);
        cc = __fmaf_rn(c4, c4, cc);
        s_candA[rank] = make_float4(__fmul_rn(-2.0f, c0), __fmul_rn(-2.0f, c1),
                                    __fmul_rn(-2.0f, c2), __fmul_rn(-2.0f, c3));
        s_candB[rank] = make_float2(__fmul_rn(-2.0f, c4), cc);
        s_jidx[rank] = (unsigned char)tid;
        s_sminS[rank] = smin;
    }
    __syncthreads();

    // compact warp regions: warp covers 32x8 px (8 patch-cols x 4 patch-rows)
    int w    = tid >> 5;
    int lane = tid & 31;
    int patch_x = (lane & 7) | ((w & 1) << 3);   // 0..15
    int patch_y = (lane >> 3) | ((w >> 1) << 2); // 0..15
    int x0 = tileX + (patch_x << 2);
    int y0 = tileY + (patch_y << 1);

    const float* xr = x + (size_t)b * 3 * NPIX;
    const float* xg = xr + NPIX;
    const float* xb = xr + 2 * NPIX;

    float fxc[4], fy[2];
#pragma unroll
    for (int i = 0; i < 4; i++) fxc[i] = __fmul_rn((float)(x0 + i), fr);
#pragma unroll
    for (int i = 0; i < 2; i++) fy[i] = __fmul_rn((float)(y0 + i), fr);

    // load the 4x2 patch (3 channels)
    float4 Rr[2], Gr[2], Br[2];
#pragma unroll
    for (int r = 0; r < 2; r++) {
        Rr[r] = *(const float4*)(xr + (y0 + r) * Ww + x0);
        Gr[r] = *(const float4*)(xg + (y0 + r) * Ww + x0);
        Br[r] = *(const float4*)(xb + (y0 + r) * Ww + x0);
    }

    float dmin[8];
    int   lab[8];
#pragma unroll
    for (int p = 0; p < 8; p++) { dmin[p] = 3.4e38f; lab[p] = 0; }

    // sorted candidates, fixed 8-cand rounds, provably-exact early exit
    int rounds = (C + 7) >> 3;
#pragma unroll 1
    for (int rd = 0; rd < rounds; rd++) {
        if (rd > 0) {
            // exit if every remaining (sorted) candidate provably loses
            float nextMin = s_sminS[rd << 3];
            float worst = -3.4e38f;
#pragma unroll
            for (int p = 0; p < 8; p++) {
                int r = p >> 2, q = p & 3;
                float f2 = __fmaf_rn(fy[r], fy[r], __fmul_rn(fxc[q], fxc[q]));
                f2 = __fmaf_rn(((const float*)&Rr[r])[q], ((const float*)&Rr[r])[q], f2);
                f2 = __fmaf_rn(((const float*)&Gr[r])[q], ((const float*)&Gr[r])[q], f2);
                f2 = __fmaf_rn(((const float*)&Br[r])[q], ((const float*)&Br[r])[q], f2);
                worst = fmaxf(worst, dmin[p] + f2);
            }
            if (__all_sync(0xffffffffu, worst + 0.25f < nextMin)) break;
        }
        int cbase = rd << 3;
#pragma unroll
        for (int i = 0; i < 8; i++) {
            int c = cbase + i;
            float4 cA = s_candA[c];
            float2 cB = s_candB[c];
            float e0 = __fmaf_rn(cA.w, fy[0], cB.y);
            float e1 = __fmaf_rn(cA.w, fy[1], cB.y);
#pragma unroll
            for (int r = 0; r < 2; r++) {
                float er = (r == 0) ? e0 : e1;
                const float* Rp = (const float*)&Rr[r];
                const float* Gp = (const float*)&Gr[r];
                const float* Bp = (const float*)&Br[r];
#pragma unroll
                for (int q = 0; q < 4; q++) {
                    float d = __fmaf_rn(cB.x, fxc[q], er);
                    d = __fmaf_rn(cA.x, Rp[q], d);
                    d = __fmaf_rn(cA.y, Gp[q], d);
                    d = __fmaf_rn(cA.z, Bp[q], d);
                    int p = r * 4 + q;
                    if (d < dmin[p]) { dmin[p] = d; lab[p] = c; }
                }
            }
        }
    }

    if (storeLabels) {
#pragma unroll
        for (int r = 0; r < 2; r++) {
            uchar4 L4 = make_uchar4(s_jidx[lab[r * 4 + 0]], s_jidx[lab[r * 4 + 1]],
                                    s_jidx[lab[r * 4 + 2]], s_jidx[lab[r * 4 + 3]]);
            *(uchar4*)&g_labels[b][(y0 + r) * Ww + x0] = L4;
        }
    }

    // ---- warp-aggregated reduction ----
    unsigned int pmLo = 0, pmHi = 0;
#pragma unroll
    for (int p = 0; p < 8; p++) {
        int l = lab[p];
        if (l < 32) pmLo |= (1u << l);
        else        pmHi |= (1u << (l - 32));
    }
    pmLo = __reduce_or_sync(0xffffffffu, pmLo);
    pmHi = __reduce_or_sync(0xffffffffu, pmHi);

    double* gacc = (double*)g_accum[it + 1][b];
    double frd = (double)fr;

#pragma unroll 1
    for (int half = 0; half < 2; half++) {
        unsigned int m = (half == 0) ? pmLo : pmHi;
        int cofs = (half == 0) ? 0 : 32;
        while (m) {
            int c = __ffs(m) - 1;
            m &= (m - 1u);
            int slot = c + cofs;
            // predicated partials: floats for RGB, EXACT ints for cnt/Y/X
            float sR = 0.f, sG = 0.f, sB = 0.f;
            unsigned int icnt = 0, iy = 0, ix = 0;
#pragma unroll
            for (int p = 0; p < 8; p++) {
                int r = p >> 2, q = p & 3;
                bool hit = (lab[p] == slot);
                float mm = hit ? 1.0f : 0.0f;
                sR = __fmaf_rn(mm, ((const float*)&Rr[r])[q], sR);
                sG = __fmaf_rn(mm, ((const float*)&Gr[r])[q], sG);
                sB = __fmaf_rn(mm, ((const float*)&Br[r])[q], sB);
                if (hit) { icnt += 1u; iy += (unsigned)(y0 + r); ix += (unsigned)(x0 + q); }
            }
#pragma unroll
            for (int off = 16; off > 0; off >>= 1) {
                sR += __shfl_xor_sync(0xffffffffu, sR, off);
                sG += __shfl_xor_sync(0xffffffffu, sG, off);
                sB += __shfl_xor_sync(0xffffffffu, sB, off);
            }
            icnt = __reduce_add_sync(0xffffffffu, icnt);
            iy   = __reduce_add_sync(0xffffffffu, iy);
            ix   = __reduce_add_sync(0xffffffffu, ix);
            if (lane == 0 && icnt != 0u) {
                int jj = s_jidx[slot];
                atomicAdd(&gacc[jj * 6 + 0], (double)sR);
                atomicAdd(&gacc[jj * 6 + 1], (double)sG);
                atomicAdd(&gacc[jj * 6 + 2], (double)sB);
                atomicAdd(&gacc[jj * 6 + 3], frd * (double)iy);
                atomicAdd(&gacc[jj * 6 + 4], frd * (double)ix);
                atomicAdd(&gacc[jj * 6 + 5], (double)icnt);
            }
        }
    }
}

// ---------------------------------------------------------------------------
// weighted color sum: w = 1/max(cnt,1) (fp32, like JAX); per-thread fp32
// partial (4 products), widened to double in the warp reduction + atomic.
// Counts come from the final assign pass's slab (SLIC_ITERS+1).
// ---------------------------------------------------------------------------
__global__ __launch_bounds__(256) void weight_kernel(const float* __restrict__ x) {
    __shared__ float s_inv[KK];
    int b   = blockIdx.y;
    int tid = threadIdx.x;
    if (tid < KK) {
        float cnt = (float)g_accum[SLIC_ITERS + 1][b][tid][5];
        cnt = fmaxf(cnt, 1.0f);
        s_inv[tid] = __fdiv_rn(1.0f, cnt);
    }
    __syncthreads();

    int idx = (blockIdx.x * 256 + tid) * 4;
    const float* xr = x + (size_t)b * 3 * NPIX;
    const float* xg = xr + NPIX;
    const float* xb = xr + 2 * NPIX;
    float4 R  = *(const float4*)(xr + idx);
    float4 G  = *(const float4*)(xg + idx);
    float4 Bc = *(const float4*)(xb + idx);
    uchar4 L  = *(const uchar4*)&g_labels[b][idx];

    float w0 = s_inv[L.x], w1 = s_inv[L.y], w2 = s_inv[L.z], w3 = s_inv[L.w];
    float frt = __fadd_rn(__fadd_rn(__fmul_rn(R.x, w0), __fmul_rn(R.y, w1)),
                          __fadd_rn(__fmul_rn(R.z, w2), __fmul_rn(R.w, w3)));
    float fgt = __fadd_rn(__fadd_rn(__fmul_rn(G.x, w0), __fmul_rn(G.y, w1)),
                          __fadd_rn(__fmul_rn(G.z, w2), __fmul_rn(G.w, w3)));
    float fbt = __fadd_rn(__fadd_rn(__fmul_rn(Bc.x, w0), __fmul_rn(Bc.y, w1)),
                          __fadd_rn(__fmul_rn(Bc.z, w2), __fmul_rn(Bc.w, w3)));
    double sr = (double)frt, sg = (double)fgt, sb = (double)fbt;
#pragma unroll
    for (int off = 16; off > 0; off >>= 1) {
        sr += __shfl_down_sync(0xffffffffu, sr, off);
        sg += __shfl_down_sync(0xffffffffu, sg, off);
        sb += __shfl_down_sync(0xffffffffu, sb, off);
    }
    if ((tid & 31) == 0) {
        atomicAdd(&g_colorsum[b][0], sr);
        atomicAdd(&g_colorsum[b][1], sg);
        atomicAdd(&g_colorsum[b][2], sb);
    }
}

// ---------------------------------------------------------------------------
// finalize: fp32 epilogue mirroring the reference formula
// ---------------------------------------------------------------------------
__global__ void finalize_kernel(float* __restrict__ out) {
    int b = threadIdx.x;
    if (b < BB) {
        float mr = (float)(g_colorsum[b][0] / (double)NPIX);
        float mg = (float)(g_colorsum[b][1] / (double)NPIX);
        float mb = (float)(g_colorsum[b][2] / (double)NPIX);
        float drg = __fadd_rn(mr, -mg);
        float drb = __fadd_rn(mr, -mb);
        float dgb = __fadd_rn(mb, -mg);
        float Drg = __fmul_rn(drg, drg);
        float Drb = __fmul_rn(drb, drb);
        float Dgb = __fmul_rn(dgb, dgb);
        float t = __fadd_rn(__fadd_rn(__fmul_rn(Drg, Drg), __fmul_rn(Drb, Drb)),
                            __fmul_rn(Dgb, Dgb));
        out[b] = __fsqrt_rn(t);
    }
}

// ---------------------------------------------------------------------------
extern "C" void kernel_launch(void* const* d_in, const int* in_sizes, int n_in,
                              void* d_out, int out_size) {
    const float* x = (const float*)d_in[0];
    float* out = (float*)d_out;

    init_kernel<<<BB, 512>>>(x);
    for (int it = 0; it < SLIC_ITERS; it++)
        assign_kernel<<<dim3(128, BB), 256>>>(x, it, 0);
    assign_kernel<<<dim3(128, BB), 256>>>(x, SLIC_ITERS, 1);  // final: labels+counts
    weight_kernel<<<dim3(256, BB), 256>>>(x);
    finalize_kernel<<<1, 32>>>(out);
}

// round 14
// speedup vs baseline: 1.2581x; 1.2581x over previous
#include <cuda_runtime.h>
#include <math.h>

#define Hh 512
#define Ww 512
#define NPIX (512*512)
#define KK 50
#define BB 16
#define SLIC_ITERS 10
#define NSLAB (SLIC_ITERS + 2)     // 12: slab it = input of assign pass it

// scratch (static device arrays; no dynamic allocation allowed)
__device__ double        g_accum[NSLAB][BB][KK][6]; // [0..4]=feat sums, [5]=count
__device__ unsigned char g_labels[BB][NPIX];
__device__ double        g_colorsum[BB][3];

__device__ __forceinline__ float ratio_f() {
    return (float)(10.0 / sqrt((double)NPIX / (double)KK));
}

// packed f32x2 helpers (Blackwell sm_100+; per-half rounding == scalar FFMA)
#define FMA_X2(out, a, b, c) \
    asm("fma.rn.f32x2 %0, %1, %2, %3;" : "=l"(out) : "l"(a), "l"(b), "l"(c))
#define PACK_X2(out, lo, hi) \
    asm("mov.b64 %0, {%1, %2};" : "=l"(out) : "f"(lo), "f"(hi))
#define UNPACK_X2(lo, hi, in) \
    asm("mov.b64 {%0, %1}, %2;" : "=f"(lo), "=f"(hi) : "l"(in))

// ---------------------------------------------------------------------------
// init: zero ALL accumulator slabs, seed slab 0 with {feat, cnt=1} so that
// centers0 = feat/1 exactly (grid-initialized, first 50 of 8x8 grid)
// ---------------------------------------------------------------------------
__global__ void init_kernel(const float* __restrict__ x) {
    int b = blockIdx.x;
    int tid = threadIdx.x;
    for (int i = tid; i < NSLAB * KK * 6; i += 512) {
        int slab = i / (KK * 6);
        int rem  = i - slab * (KK * 6);
        g_accum[slab][b][rem / 6][rem % 6] = 0.0;
    }
    if (b == 0 && tid >= 448 && tid < 448 + BB * 3) ((double*)g_colorsum)[tid - 448] = 0.0;
    __syncthreads();
    if (tid < KK) {
        int i = tid >> 3, j = tid & 7;
        int y = 32 + 64 * i;
        int xc = 32 + 64 * j;
        const float* xb = x + (size_t)b * 3 * NPIX;
        float r  = xb[y * Ww + xc];
        float g  = xb[NPIX + y * Ww + xc];
        float bl = xb[2 * NPIX + y * Ww + xc];
        float fr = ratio_f();
        double* a = g_accum[0][b][tid];
        a[0] = (double)r;
        a[1] = (double)g;
        a[2] = (double)bl;
        a[3] = (double)__fmul_rn((float)y, fr);
        a[4] = (double)__fmul_rn((float)xc, fr);
        a[5] = 1.0;
    }
}

// ---------------------------------------------------------------------------
// assign pass it (R12 structure + packed f32x2 mainloop):
// centers computed IN-PROLOGUE from g_accum[it] (fp32 divide, JAX-style);
// segment sums atomically added to g_accum[it+1].
// Block = 64x32 tile; 1 thread = 4x2 patch; warp covers a compact 32x8 region.
// Exact spatial pruning: candidate iff smin_j <= min(smax) + 3 [+pad].
// Candidates compacted ascending-j; +INF sentinel; fixed 8-candidate rounds.
// Candidate constants stored PRE-BROADCAST as {c,c} f32x2 pairs in shared, so
// the mainloop does pure packed FMA: distances bit-identical to scalar.
// Reduction: warp aggregation; RGB shfl tree; cnt/Y/X exact ints via REDUX;
// lane 0 alone issues global f64 atomics.
// ---------------------------------------------------------------------------
__global__ __launch_bounds__(256, 3) void assign_kernel(const float* __restrict__ x,
                                                        int it, int storeLabels) {
    __shared__ ulonglong2 s_pkA[64];          // {(-2c0,-2c0), (-2c1,-2c1)}
    __shared__ ulonglong2 s_pkB[64];          // {(-2c2,-2c2), (-2c3,-2c3)}
    __shared__ ulonglong2 s_pkC[64];          // {(-2c4,-2c4), (cc,cc) | +INF}
    __shared__ unsigned char s_jidx[64];
    __shared__ float s_smax[64];
    __shared__ unsigned int s_mask[2];
    __shared__ float s_T;

    int b   = blockIdx.y;
    int tid = threadIdx.x;
    int tileX = (blockIdx.x & 7) << 6;        // 8 x-tiles of 64
    int tileY = (blockIdx.x >> 3) << 5;       // 16 y-tiles of 32

    float fr = ratio_f();
    float byLo = __fmul_rn((float)tileY, fr);
    float byHi = __fmul_rn((float)(tileY + 31), fr);
    float bxLo = __fmul_rn((float)tileX, fr);
    float bxHi = __fmul_rn((float)(tileX + 63), fr);

    float c0 = 0.f, c1 = 0.f, c2 = 0.f, c3 = 0.f, c4 = 0.f, smin = 0.f;
    if (tid < 64) {
        // sentinel: zero multipliers, +INF base -> d = +INF, never selected
        s_pkA[tid] = make_ulonglong2(0ull, 0ull);
        s_pkB[tid] = make_ulonglong2(0ull, 0ull);
        s_pkC[tid] = make_ulonglong2(0ull, 0x7f8000007f800000ull);
        s_jidx[tid] = 0;
        s_smax[tid] = 3.4e38f;
    }
    if (tid < KK) {
        // centers from previous pass's sums (fused update, JAX-style fp32 div)
        const double* a = g_accum[it][b][tid];
        float fcnt = fmaxf((float)a[5], 1.0f);
        c0 = __fdiv_rn((float)a[0], fcnt);
        c1 = __fdiv_rn((float)a[1], fcnt);
        c2 = __fdiv_rn((float)a[2], fcnt);
        c3 = __fdiv_rn((float)a[3], fcnt);
        c4 = __fdiv_rn((float)a[4], fcnt);
        float dyo = fmaxf(fmaxf(byLo - c3, c3 - byHi), 0.0f);
        float dxo = fmaxf(fmaxf(bxLo - c4, c4 - bxHi), 0.0f);
        smin = dyo * dyo + dxo * dxo;
        float dyM = fmaxf(fabsf(c3 - byLo), fabsf(c3 - byHi));
        float dxM = fmaxf(fabsf(c4 - bxLo), fabsf(c4 - bxHi));
        s_smax[tid] = dyM * dyM + dxM * dxM;
    }
    __syncthreads();
    if (tid < 32) {                        // warp-parallel min reduction
        float v = fminf(s_smax[tid], s_smax[tid + 32]);
#pragma unroll
        for (int off = 16; off > 0; off >>= 1)
            v = fminf(v, __shfl_xor_sync(0xffffffffu, v, off));
        if (tid == 0) s_T = v + 3.0f + 1e-3f;  // color slack + fp pad
    }
    __syncthreads();
    bool keep = (tid < KK) && (smin <= s_T);
    unsigned int wm = __ballot_sync(0xffffffffu, keep);
    if (tid < 64 && (tid & 31) == 0) s_mask[tid >> 5] = wm;
    __syncthreads();
    unsigned int m0 = s_mask[0], m1 = s_mask[1];
    if (keep) {
        unsigned int mm = (tid < 32) ? m0 : m1;
        int base = (tid < 32) ? 0 : __popc(m0);
        int pos = base + __popc(mm & ((1u << (tid & 31)) - 1u));
        float cc = __fmul_rn(c0, c0);
        cc = __fmaf_rn(c1, c1, cc);
        cc = __fmaf_rn(c2, c2, cc);
        cc = __fmaf_rn(c3, c3, cc);
        cc = __fmaf_rn(c4, c4, cc);
        float n0 = __fmul_rn(-2.0f, c0), n1 = __fmul_rn(-2.0f, c1);
        float n2 = __fmul_rn(-2.0f, c2), n3 = __fmul_rn(-2.0f, c3);
        float n4 = __fmul_rn(-2.0f, c4);
        unsigned long long p0, p1, p2, p3, p4, p5;
        PACK_X2(p0, n0, n0); PACK_X2(p1, n1, n1);
        PACK_X2(p2, n2, n2); PACK_X2(p3, n3, n3);
        PACK_X2(p4, n4, n4); PACK_X2(p5, cc, cc);
        s_pkA[pos] = make_ulonglong2(p0, p1);
        s_pkB[pos] = make_ulonglong2(p2, p3);
        s_pkC[pos] = make_ulonglong2(p4, p5);
        s_jidx[pos] = (unsigned char)tid;
    }
    int C = __popc(m0) + __popc(m1);
    __syncthreads();

    // compact warp regions: warp covers 32x8 px (8 patch-cols x 4 patch-rows)
    int w    = tid >> 5;
    int lane = tid & 31;
    int patch_x = (lane & 7) | ((w & 1) << 3);   // 0..15
    int patch_y = (lane >> 3) | ((w >> 1) << 2); // 0..15
    int x0 = tileX + (patch_x << 2);
    int y0 = tileY + (patch_y << 1);

    const float* xr = x + (size_t)b * 3 * NPIX;
    const float* xg = xr + NPIX;
    const float* xb = xr + 2 * NPIX;

    float fxc[4], fy[2];
#pragma unroll
    for (int i = 0; i < 4; i++) fxc[i] = __fmul_rn((float)(x0 + i), fr);
#pragma unroll
    for (int i = 0; i < 2; i++) fy[i] = __fmul_rn((float)(y0 + i), fr);

    // load the 4x2 patch (3 channels) and pack pixel pairs (q01, q23 per row)
    float4 Rr[2], Gr[2], Br[2];
#pragma unroll
    for (int r = 0; r < 2; r++) {
        Rr[r] = *(const float4*)(xr + (y0 + r) * Ww + x0);
        Gr[r] = *(const float4*)(xg + (y0 + r) * Ww + x0);
        Br[r] = *(const float4*)(xb + (y0 + r) * Ww + x0);
    }
    unsigned long long PR[4], PG[4], PB[4], FX[2], FY[2];
#pragma unroll
    for (int r = 0; r < 2; r++) {
        PACK_X2(PR[r * 2 + 0], Rr[r].x, Rr[r].y);
        PACK_X2(PR[r * 2 + 1], Rr[r].z, Rr[r].w);
        PACK_X2(PG[r * 2 + 0], Gr[r].x, Gr[r].y);
        PACK_X2(PG[r * 2 + 1], Gr[r].z, Gr[r].w);
        PACK_X2(PB[r * 2 + 0], Br[r].x, Br[r].y);
        PACK_X2(PB[r * 2 + 1], Br[r].z, Br[r].w);
        PACK_X2(FY[r], fy[r], fy[r]);
    }
    PACK_X2(FX[0], fxc[0], fxc[1]);
    PACK_X2(FX[1], fxc[2], fxc[3]);

    float dmin[8];
    int   lab[8];
#pragma unroll
    for (int p = 0; p < 8; p++) { dmin[p] = 3.4e38f; lab[p] = 0; }

    // fixed-trip unrolled rounds of 8 candidates (sentinel-padded, exact);
    // packed f32x2 distance math, per-half rounding == scalar FFMA
    int rounds = (C + 7) >> 3;             // 1-2 typically
    for (int rd = 0; rd < rounds; rd++) {
        int cbase = rd << 3;
#pragma unroll
        for (int i = 0; i < 8; i++) {
            int c = cbase + i;
            ulonglong2 pa = s_pkA[c];      // {n0n0, n1n1}
            ulonglong2 pb = s_pkB[c];      // {n2n2, n3n3}
            ulonglong2 pc = s_pkC[c];      // {n4n4, cccc}
            unsigned long long er0, er1;
            FMA_X2(er0, pb.y, FY[0], pc.y);
            FMA_X2(er1, pb.y, FY[1], pc.y);
#pragma unroll
            for (int r = 0; r < 2; r++) {
                unsigned long long er = (r == 0) ? er0 : er1;
#pragma unroll
                for (int h = 0; h < 2; h++) {
                    unsigned long long D;
                    FMA_X2(D, pc.x, FX[h], er);
                    FMA_X2(D, pa.x, PR[r * 2 + h], D);
                    FMA_X2(D, pa.y, PG[r * 2 + h], D);
                    FMA_X2(D, pb.x, PB[r * 2 + h], D);
                    float d0, d1;
                    UNPACK_X2(d0, d1, D);
                    int p = r * 4 + h * 2;
                    if (d0 < dmin[p])     { dmin[p] = d0;     lab[p] = c; }
                    if (d1 < dmin[p + 1]) { dmin[p + 1] = d1; lab[p + 1] = c; }
                }
            }
        }
    }

    if (storeLabels) {
#pragma unroll
        for (int r = 0; r < 2; r++) {
            uchar4 L4 = make_uchar4(s_jidx[lab[r * 4 + 0]], s_jidx[lab[r * 4 + 1]],
                                    s_jidx[lab[r * 4 + 2]], s_jidx[lab[r * 4 + 3]]);
            *(uchar4*)&g_labels[b][(y0 + r) * Ww + x0] = L4;
        }
    }

    // ---- warp-aggregated reduction ----
    unsigned int pmLo = 0, pmHi = 0;
#pragma unroll
    for (int p = 0; p < 8; p++) {
        int l = lab[p];
        if (l < 32) pmLo |= (1u << l);
        else        pmHi |= (1u << (l - 32));
    }
    pmLo = __reduce_or_sync(0xffffffffu, pmLo);
    pmHi = __reduce_or_sync(0xffffffffu, pmHi);

    double* gacc = (double*)g_accum[it + 1][b];
    double frd = (double)fr;

#pragma unroll 1
    for (int half = 0; half < 2; half++) {
        unsigned int m = (half == 0) ? pmLo : pmHi;
        int cofs = (half == 0) ? 0 : 32;
        while (m) {
            int c = __ffs(m) - 1;
            m &= (m - 1u);
            int slot = c + cofs;
            // predicated partials: floats for RGB, EXACT ints for cnt/Y/X
            float sR = 0.f, sG = 0.f, sB = 0.f;
            unsigned int icnt = 0, iy = 0, ix = 0;
#pragma unroll
            for (int p = 0; p < 8; p++) {
                int r = p >> 2, q = p & 3;
                bool hit = (lab[p] == slot);
                float mm = hit ? 1.0f : 0.0f;
                sR = __fmaf_rn(mm, ((const float*)&Rr[r])[q], sR);
                sG = __fmaf_rn(mm, ((const float*)&Gr[r])[q], sG);
                sB = __fmaf_rn(mm, ((const float*)&Br[r])[q], sB);
                if (hit) { icnt += 1u; iy += (unsigned)(y0 + r); ix += (unsigned)(x0 + q); }
            }
            // R,G,B: shfl tree (deterministic); cnt/Y/X: hardware REDUX
#pragma unroll
            for (int off = 16; off > 0; off >>= 1) {
                sR += __shfl_xor_sync(0xffffffffu, sR, off);
                sG += __shfl_xor_sync(0xffffffffu, sG, off);
                sB += __shfl_xor_sync(0xffffffffu, sB, off);
            }
            icnt = __reduce_add_sync(0xffffffffu, icnt);
            iy   = __reduce_add_sync(0xffffffffu, iy);
            ix   = __reduce_add_sync(0xffffffffu, ix);
            if (lane == 0 && icnt != 0u) {
                int jj = s_jidx[slot];
                atomicAdd(&gacc[jj * 6 + 0], (double)sR);
                atomicAdd(&gacc[jj * 6 + 1], (double)sG);
                atomicAdd(&gacc[jj * 6 + 2], (double)sB);
                atomicAdd(&gacc[jj * 6 + 3], frd * (double)iy);
                atomicAdd(&gacc[jj * 6 + 4], frd * (double)ix);
                atomicAdd(&gacc[jj * 6 + 5], (double)icnt);
            }
        }
    }
}

// ---------------------------------------------------------------------------
// weighted color sum: w = 1/max(cnt,1) (fp32, like JAX); per-thread fp32
// partial (4 products), widened to double in the warp reduction + atomic.
// Counts come from the final assign pass's slab (SLIC_ITERS+1).
// ---------------------------------------------------------------------------
__global__ __launch_bounds__(256) void weight_kernel(const float* __restrict__ x) {
    __shared__ float s_inv[KK];
    int b   = blockIdx.y;
    int tid = threadIdx.x;
    if (tid < KK) {
        float cnt = (float)g_accum[SLIC_ITERS + 1][b][tid][5];
        cnt = fmaxf(cnt, 1.0f);
        s_inv[tid] = __fdiv_rn(1.0f, cnt);
    }
    __syncthreads();

    int idx = (blockIdx.x * 256 + tid) * 4;
    const float* xr = x + (size_t)b * 3 * NPIX;
    const float* xg = xr + NPIX;
    const float* xb = xr + 2 * NPIX;
    float4 R  = *(const float4*)(xr + idx);
    float4 G  = *(const float4*)(xg + idx);
    float4 Bc = *(const float4*)(xb + idx);
    uchar4 L  = *(const uchar4*)&g_labels[b][idx];

    float w0 = s_inv[L.x], w1 = s_inv[L.y], w2 = s_inv[L.z], w3 = s_inv[L.w];
    float frt = __fadd_rn(__fadd_rn(__fmul_rn(R.x, w0), __fmul_rn(R.y, w1)),
                          __fadd_rn(__fmul_rn(R.z, w2), __fmul_rn(R.w, w3)));
    float fgt = __fadd_rn(__fadd_rn(__fmul_rn(G.x, w0), __fmul_rn(G.y, w1)),
                          __fadd_rn(__fmul_rn(G.z, w2), __fmul_rn(G.w, w3)));
    float fbt = __fadd_rn(__fadd_rn(__fmul_rn(Bc.x, w0), __fmul_rn(Bc.y, w1)),
                          __fadd_rn(__fmul_rn(Bc.z, w2), __fmul_rn(Bc.w, w3)));
    double sr = (double)frt, sg = (double)fgt, sb = (double)fbt;
#pragma unroll
    for (int off = 16; off > 0; off >>= 1) {
        sr += __shfl_down_sync(0xffffffffu, sr, off);
        sg += __shfl_down_sync(0xffffffffu, sg, off);
        sb += __shfl_down_sync(0xffffffffu, sb, off);
    }
    if ((tid & 31) == 0) {
        atomicAdd(&g_colorsum[b][0], sr);
        atomicAdd(&g_colorsum[b][1], sg);
        atomicAdd(&g_colorsum[b][2], sb);
    }
}

// ---------------------------------------------------------------------------
// finalize: fp32 epilogue mirroring the reference formula
// ---------------------------------------------------------------------------
__global__ void finalize_kernel(float* __restrict__ out) {
    int b = threadIdx.x;
    if (b < BB) {
        float mr = (float)(g_colorsum[b][0] / (double)NPIX);
        float mg = (float)(g_colorsum[b][1] / (double)NPIX);
        float mb = (float)(g_colorsum[b][2] / (double)NPIX);
        float drg = __fadd_rn(mr, -mg);
        float drb = __fadd_rn(mr, -mb);
        float dgb = __fadd_rn(mb, -mg);
        float Drg = __fmul_rn(drg, drg);
        float Drb = __fmul_rn(drb, drb);
        float Dgb = __fmul_rn(dgb, dgb);
        float t = __fadd_rn(__fadd_rn(__fmul_rn(Drg, Drg), __fmul_rn(Drb, Drb)),
                            __fmul_rn(Dgb, Dgb));
        out[b] = __fsqrt_rn(t);
    }
}

// ---------------------------------------------------------------------------
extern "C" void kernel_launch(void* const* d_in, const int* in_sizes, int n_in,
                              void* d_out, int out_size) {
    const float* x = (const float*)d_in[0];
    float* out = (float*)d_out;

    init_kernel<<<BB, 512>>>(x);
    for (int it = 0; it < SLIC_ITERS; it++)
        assign_kernel<<<dim3(128, BB), 256>>>(x, it, 0);
    assign_kernel<<<dim3(128, BB), 256>>>(x, SLIC_ITERS, 1);  // final: labels+counts
    weight_kernel<<<dim3(256, BB), 256>>>(x);
    finalize_kernel<<<1, 32>>>(out);
}

// round 15
// speedup vs baseline: 1.6281x; 1.2941x over previous
#include <cuda_runtime.h>
#include <math.h>

#define Hh 512
#define Ww 512
#define NPIX (512*512)
#define KK 50
#define BB 16
#define SLIC_ITERS 10
#define NSLAB (SLIC_ITERS + 2)     // 12: slab it = input of assign pass it

// scratch (static device arrays; no dynamic allocation allowed)
__device__ double g_accum[NSLAB][BB][KK][6]; // [0..4]=feat sums, [5]=count

__device__ __forceinline__ float ratio_f() {
    return (float)(10.0 / sqrt((double)NPIX / (double)KK));
}

// packed f32x2 helpers (Blackwell sm_100+; per-half rounding == scalar FFMA)
#define FMA_X2(out, a, b, c) \
    asm("fma.rn.f32x2 %0, %1, %2, %3;" : "=l"(out) : "l"(a), "l"(b), "l"(c))
#define PACK_X2(out, lo, hi) \
    asm("mov.b64 %0, {%1, %2};" : "=l"(out) : "f"(lo), "f"(hi))
#define UNPACK_X2(lo, hi, in) \
    asm("mov.b64 {%0, %1}, %2;" : "=f"(lo), "=f"(hi) : "l"(in))

// ---------------------------------------------------------------------------
// init: zero ALL accumulator slabs, seed slab 0 with {feat, cnt=1} so that
// centers0 = feat/1 exactly (grid-initialized, first 50 of 8x8 grid)
// ---------------------------------------------------------------------------
__global__ void init_kernel(const float* __restrict__ x) {
    int b = blockIdx.x;
    int tid = threadIdx.x;
    for (int i = tid; i < NSLAB * KK * 6; i += 512) {
        int slab = i / (KK * 6);
        int rem  = i - slab * (KK * 6);
        g_accum[slab][b][rem / 6][rem % 6] = 0.0;
    }
    __syncthreads();
    if (tid < KK) {
        int i = tid >> 3, j = tid & 7;
        int y = 32 + 64 * i;
        int xc = 32 + 64 * j;
        const float* xb = x + (size_t)b * 3 * NPIX;
        float r  = xb[y * Ww + xc];
        float g  = xb[NPIX + y * Ww + xc];
        float bl = xb[2 * NPIX + y * Ww + xc];
        float fr = ratio_f();
        double* a = g_accum[0][b][tid];
        a[0] = (double)r;
        a[1] = (double)g;
        a[2] = (double)bl;
        a[3] = (double)__fmul_rn((float)y, fr);
        a[4] = (double)__fmul_rn((float)xc, fr);
        a[5] = 1.0;
    }
}

// ---------------------------------------------------------------------------
// assign pass it (R14 structure + patch prefetch, labels never stored):
// centers computed IN-PROLOGUE from g_accum[it] (fp32 divide, JAX-style);
// segment sums atomically added to g_accum[it+1].  The weighted-mean output
// is recovered in finalize from slab SLIC_ITERS+1 (sum_k segsum_k/cnt_k), so
// no labels or weight pass exist at all.
// Block = 64x32 tile; 1 thread = 4x2 patch; warp covers a compact 32x8 region.
// Patch LDGs issued BEFORE the prologue barriers (overlap DRAM latency).
// Exact spatial pruning: candidate iff smin_j <= min(smax) + 3 [+pad].
// Candidates compacted ascending-j; +INF sentinel; fixed 8-candidate rounds;
// packed f32x2 distance math (bit-identical to scalar FFMA).
// Reduction: warp aggregation; RGB shfl tree; cnt/Y/X exact ints via REDUX;
// lane 0 alone issues global f64 atomics.
// ---------------------------------------------------------------------------
__global__ __launch_bounds__(256, 3) void assign_kernel(const float* __restrict__ x,
                                                        int it) {
    __shared__ ulonglong2 s_pkA[64];          // {(-2c0,-2c0), (-2c1,-2c1)}
    __shared__ ulonglong2 s_pkB[64];          // {(-2c2,-2c2), (-2c3,-2c3)}
    __shared__ ulonglong2 s_pkC[64];          // {(-2c4,-2c4), (cc,cc) | +INF}
    __shared__ unsigned char s_jidx[64];
    __shared__ float s_smax[64];
    __shared__ unsigned int s_mask[2];
    __shared__ float s_T;

    int b   = blockIdx.y;
    int tid = threadIdx.x;
    int tileX = (blockIdx.x & 7) << 6;        // 8 x-tiles of 64
    int tileY = (blockIdx.x >> 3) << 5;       // 16 y-tiles of 32

    // ---- patch prefetch: issue the 6 LDG.128 before any barrier ----
    int w    = tid >> 5;
    int lane = tid & 31;
    int patch_x = (lane & 7) | ((w & 1) << 3);   // 0..15
    int patch_y = (lane >> 3) | ((w >> 1) << 2); // 0..15
    int x0 = tileX + (patch_x << 2);
    int y0 = tileY + (patch_y << 1);
    const float* xr = x + (size_t)b * 3 * NPIX;
    const float* xg = xr + NPIX;
    const float* xb = xr + 2 * NPIX;
    float4 Rr[2], Gr[2], Br[2];
#pragma unroll
    for (int r = 0; r < 2; r++) {
        Rr[r] = *(const float4*)(xr + (y0 + r) * Ww + x0);
        Gr[r] = *(const float4*)(xg + (y0 + r) * Ww + x0);
        Br[r] = *(const float4*)(xb + (y0 + r) * Ww + x0);
    }

    float fr = ratio_f();
    float byLo = __fmul_rn((float)tileY, fr);
    float byHi = __fmul_rn((float)(tileY + 31), fr);
    float bxLo = __fmul_rn((float)tileX, fr);
    float bxHi = __fmul_rn((float)(tileX + 63), fr);

    float c0 = 0.f, c1 = 0.f, c2 = 0.f, c3 = 0.f, c4 = 0.f, smin = 0.f;
    if (tid < 64) {
        // sentinel: zero multipliers, +INF base -> d = +INF, never selected
        s_pkA[tid] = make_ulonglong2(0ull, 0ull);
        s_pkB[tid] = make_ulonglong2(0ull, 0ull);
        s_pkC[tid] = make_ulonglong2(0ull, 0x7f8000007f800000ull);
        s_jidx[tid] = 0;
        s_smax[tid] = 3.4e38f;
    }
    if (tid < KK) {
        // centers from previous pass's sums (fused update, JAX-style fp32 div)
        const double* a = g_accum[it][b][tid];
        float fcnt = fmaxf((float)a[5], 1.0f);
        c0 = __fdiv_rn((float)a[0], fcnt);
        c1 = __fdiv_rn((float)a[1], fcnt);
        c2 = __fdiv_rn((float)a[2], fcnt);
        c3 = __fdiv_rn((float)a[3], fcnt);
        c4 = __fdiv_rn((float)a[4], fcnt);
        float dyo = fmaxf(fmaxf(byLo - c3, c3 - byHi), 0.0f);
        float dxo = fmaxf(fmaxf(bxLo - c4, c4 - bxHi), 0.0f);
        smin = dyo * dyo + dxo * dxo;
        float dyM = fmaxf(fabsf(c3 - byLo), fabsf(c3 - byHi));
        float dxM = fmaxf(fabsf(c4 - bxLo), fabsf(c4 - bxHi));
        s_smax[tid] = dyM * dyM + dxM * dxM;
    }
    __syncthreads();
    if (tid < 32) {                        // warp-parallel min reduction
        float v = fminf(s_smax[tid], s_smax[tid + 32]);
#pragma unroll
        for (int off = 16; off > 0; off >>= 1)
            v = fminf(v, __shfl_xor_sync(0xffffffffu, v, off));
        if (tid == 0) s_T = v + 3.0f + 1e-3f;  // color slack + fp pad
    }
    __syncthreads();
    bool keep = (tid < KK) && (smin <= s_T);
    unsigned int wm = __ballot_sync(0xffffffffu, keep);
    if (tid < 64 && (tid & 31) == 0) s_mask[tid >> 5] = wm;
    __syncthreads();
    unsigned int m0 = s_mask[0], m1 = s_mask[1];
    if (keep) {
        unsigned int mm = (tid < 32) ? m0 : m1;
        int base = (tid < 32) ? 0 : __popc(m0);
        int pos = base + __popc(mm & ((1u << (tid & 31)) - 1u));
        float cc = __fmul_rn(c0, c0);
        cc = __fmaf_rn(c1, c1, cc);
        cc = __fmaf_rn(c2, c2, cc);
        cc = __fmaf_rn(c3, c3, cc);
        cc = __fmaf_rn(c4, c4, cc);
        float n0 = __fmul_rn(-2.0f, c0), n1 = __fmul_rn(-2.0f, c1);
        float n2 = __fmul_rn(-2.0f, c2), n3 = __fmul_rn(-2.0f, c3);
        float n4 = __fmul_rn(-2.0f, c4);
        unsigned long long p0, p1, p2, p3, p4, p5;
        PACK_X2(p0, n0, n0); PACK_X2(p1, n1, n1);
        PACK_X2(p2, n2, n2); PACK_X2(p3, n3, n3);
        PACK_X2(p4, n4, n4); PACK_X2(p5, cc, cc);
        s_pkA[pos] = make_ulonglong2(p0, p1);
        s_pkB[pos] = make_ulonglong2(p2, p3);
        s_pkC[pos] = make_ulonglong2(p4, p5);
        s_jidx[pos] = (unsigned char)tid;
    }
    int C = __popc(m0) + __popc(m1);
    __syncthreads();

    float fxc[4], fy[2];
#pragma unroll
    for (int i = 0; i < 4; i++) fxc[i] = __fmul_rn((float)(x0 + i), fr);
#pragma unroll
    for (int i = 0; i < 2; i++) fy[i] = __fmul_rn((float)(y0 + i), fr);

    // pack pixel pairs (q01, q23 per row)
    unsigned long long PR[4], PG[4], PB[4], FX[2], FY[2];
#pragma unroll
    for (int r = 0; r < 2; r++) {
        PACK_X2(PR[r * 2 + 0], Rr[r].x, Rr[r].y);
        PACK_X2(PR[r * 2 + 1], Rr[r].z, Rr[r].w);
        PACK_X2(PG[r * 2 + 0], Gr[r].x, Gr[r].y);
        PACK_X2(PG[r * 2 + 1], Gr[r].z, Gr[r].w);
        PACK_X2(PB[r * 2 + 0], Br[r].x, Br[r].y);
        PACK_X2(PB[r * 2 + 1], Br[r].z, Br[r].w);
        PACK_X2(FY[r], fy[r], fy[r]);
    }
    PACK_X2(FX[0], fxc[0], fxc[1]);
    PACK_X2(FX[1], fxc[2], fxc[3]);

    float dmin[8];
    int   lab[8];
#pragma unroll
    for (int p = 0; p < 8; p++) { dmin[p] = 3.4e38f; lab[p] = 0; }

    // fixed-trip unrolled rounds of 8 candidates (sentinel-padded, exact)
    int rounds = (C + 7) >> 3;             // 1-2 typically
    for (int rd = 0; rd < rounds; rd++) {
        int cbase = rd << 3;
#pragma unroll
        for (int i = 0; i < 8; i++) {
            int c = cbase + i;
            ulonglong2 pa = s_pkA[c];      // {n0n0, n1n1}
            ulonglong2 pb = s_pkB[c];      // {n2n2, n3n3}
            ulonglong2 pc = s_pkC[c];      // {n4n4, cccc}
            unsigned long long er0, er1;
            FMA_X2(er0, pb.y, FY[0], pc.y);
            FMA_X2(er1, pb.y, FY[1], pc.y);
#pragma unroll
            for (int r = 0; r < 2; r++) {
                unsigned long long er = (r == 0) ? er0 : er1;
#pragma unroll
                for (int h = 0; h < 2; h++) {
                    unsigned long long D;
                    FMA_X2(D, pc.x, FX[h], er);
                    FMA_X2(D, pa.x, PR[r * 2 + h], D);
                    FMA_X2(D, pa.y, PG[r * 2 + h], D);
                    FMA_X2(D, pb.x, PB[r * 2 + h], D);
                    float d0, d1;
                    UNPACK_X2(d0, d1, D);
                    int p = r * 4 + h * 2;
                    if (d0 < dmin[p])     { dmin[p] = d0;     lab[p] = c; }
                    if (d1 < dmin[p + 1]) { dmin[p + 1] = d1; lab[p + 1] = c; }
                }
            }
        }
    }

    // ---- warp-aggregated reduction ----
    unsigned int pmLo = 0, pmHi = 0;
#pragma unroll
    for (int p = 0; p < 8; p++) {
        int l = lab[p];
        if (l < 32) pmLo |= (1u << l);
        else        pmHi |= (1u << (l - 32));
    }
    pmLo = __reduce_or_sync(0xffffffffu, pmLo);
    pmHi = __reduce_or_sync(0xffffffffu, pmHi);

    double* gacc = (double*)g_accum[it + 1][b];
    double frd = (double)fr;

#pragma unroll 1
    for (int half = 0; half < 2; half++) {
        unsigned int m = (half == 0) ? pmLo : pmHi;
        int cofs = (half == 0) ? 0 : 32;
        while (m) {
            int c = __ffs(m) - 1;
            m &= (m - 1u);
            int slot = c + cofs;
            // predicated partials: floats for RGB, EXACT ints for cnt/Y/X
            float sR = 0.f, sG = 0.f, sB = 0.f;
            unsigned int icnt = 0, iy = 0, ix = 0;
#pragma unroll
            for (int p = 0; p < 8; p++) {
                int r = p >> 2, q = p & 3;
                bool hit = (lab[p] == slot);
                float mm = hit ? 1.0f : 0.0f;
                sR = __fmaf_rn(mm, ((const float*)&Rr[r])[q], sR);
                sG = __fmaf_rn(mm, ((const float*)&Gr[r])[q], sG);
                sB = __fmaf_rn(mm, ((const float*)&Br[r])[q], sB);
                if (hit) { icnt += 1u; iy += (unsigned)(y0 + r); ix += (unsigned)(x0 + q); }
            }
            // R,G,B: shfl tree (deterministic); cnt/Y/X: hardware REDUX
#pragma unroll
            for (int off = 16; off > 0; off >>= 1) {
                sR += __shfl_xor_sync(0xffffffffu, sR, off);
                sG += __shfl_xor_sync(0xffffffffu, sG, off);
                sB += __shfl_xor_sync(0xffffffffu, sB, off);
            }
            icnt = __reduce_add_sync(0xffffffffu, icnt);
            iy   = __reduce_add_sync(0xffffffffu, iy);
            ix   = __reduce_add_sync(0xffffffffu, ix);
            if (lane == 0 && icnt != 0u) {
                int jj = s_jidx[slot];
                atomicAdd(&gacc[jj * 6 + 0], (double)sR);
                atomicAdd(&gacc[jj * 6 + 1], (double)sG);
                atomicAdd(&gacc[jj * 6 + 2], (double)sB);
                atomicAdd(&gacc[jj * 6 + 3], frd * (double)iy);
                atomicAdd(&gacc[jj * 6 + 4], frd * (double)ix);
                atomicAdd(&gacc[jj * 6 + 5], (double)icnt);
            }
        }
    }
}

// ---------------------------------------------------------------------------
// finalize: weighted mean = (1/N) * sum_k segsum_k / max(cnt_k, 1)
// (algebraic identity with the reference's per-pixel w=1/cnt weighting;
//  segment sums are f64 -> accuracy >= reference). One block per batch.
// ---------------------------------------------------------------------------
__global__ void finalize_kernel(float* __restrict__ out) {
    __shared__ double s_part[2][3];
    int b   = blockIdx.x;
    int tid = threadIdx.x;          // 64 threads
    double sr = 0.0, sg = 0.0, sb = 0.0;
    if (tid < KK) {
        const double* a = g_accum[SLIC_ITERS + 1][b][tid];
        float cntf = fmaxf((float)a[5], 1.0f);
        double inv = (double)__fdiv_rn(1.0f, cntf);   // JAX-style fp32 weight
        sr = a[0] * inv;
        sg = a[1] * inv;
        sb = a[2] * inv;
    }
#pragma unroll
    for (int off = 16; off > 0; off >>= 1) {
        sr += __shfl_xor_sync(0xffffffffu, sr, off);
        sg += __shfl_xor_sync(0xffffffffu, sg, off);
        sb += __shfl_xor_sync(0xffffffffu, sb, off);
    }
    if ((tid & 31) == 0) {
        s_part[tid >> 5][0] = sr;
        s_part[tid >> 5][1] = sg;
        s_part[tid >> 5][2] = sb;
    }
    __syncthreads();
    if (tid == 0) {
        float mr = (float)((s_part[0][0] + s_part[1][0]) / (double)NPIX);
        float mg = (float)((s_part[0][1] + s_part[1][1]) / (double)NPIX);
        float mb = (float)((s_part[0][2] + s_part[1][2]) / (double)NPIX);
        float drg = __fadd_rn(mr, -mg);
        float drb = __fadd_rn(mr, -mb);
        float dgb = __fadd_rn(mb, -mg);
        float Drg = __fmul_rn(drg, drg);
        float Drb = __fmul_rn(drb, drb);
        float Dgb = __fmul_rn(dgb, dgb);
        float t = __fadd_rn(__fadd_rn(__fmul_rn(Drg, Drg), __fmul_rn(Drb, Drb)),
                            __fmul_rn(Dgb, Dgb));
        out[b] = __fsqrt_rn(t);
    }
}

// ---------------------------------------------------------------------------
extern "C" void kernel_launch(void* const* d_in, const int* in_sizes, int n_in,
                              void* d_out, int out_size) {
    const float* x = (const float*)d_in[0];
    float* out = (float*)d_out;

    init_kernel<<<BB, 512>>>(x);
    for (int it = 0; it <= SLIC_ITERS; it++)          // 11 passes; last fills slab 11
        assign_kernel<<<dim3(128, BB), 256>>>(x, it);
    finalize_kernel<<<BB, 64>>>(out);
}

// round 16
// speedup vs baseline: 1.6439x; 1.0097x over previous
#include <cuda_runtime.h>
#include <math.h>

#define Hh 512
#define Ww 512
#define NPIX (512*512)
#define KK 50
#define BB 16
#define SLIC_ITERS 10
#define NSLAB (SLIC_ITERS + 2)     // 12: slab it = input of assign pass it

// scratch (static device arrays; no dynamic allocation allowed)
__device__ double g_accum[NSLAB][BB][KK][6]; // [0..4]=feat sums, [5]=count

__device__ __forceinline__ float ratio_f() {
    return (float)(10.0 / sqrt((double)NPIX / (double)KK));
}

// packed f32x2 helpers (Blackwell sm_100+; per-half rounding == scalar FFMA)
#define FMA_X2(out, a, b, c) \
    asm("fma.rn.f32x2 %0, %1, %2, %3;" : "=l"(out) : "l"(a), "l"(b), "l"(c))
#define PACK_X2(out, lo, hi) \
    asm("mov.b64 %0, {%1, %2};" : "=l"(out) : "f"(lo), "f"(hi))
#define UNPACK_X2(lo, hi, in) \
    asm("mov.b64 {%0, %1}, %2;" : "=f"(lo), "=f"(hi) : "l"(in))

// ---------------------------------------------------------------------------
// init: zero slabs 1..NSLAB-1, seed slab 0 with {feat, cnt=1} so that
// centers0 = feat/1 exactly (grid-initialized, first 50 of 8x8 grid)
// ---------------------------------------------------------------------------
__global__ void init_kernel(const float* __restrict__ x) {
    int b = blockIdx.x;
    int tid = threadIdx.x;
    for (int i = tid; i < (NSLAB - 1) * KK * 6; i += 512) {
        int slab = 1 + i / (KK * 6);
        int rem  = i % (KK * 6);
        g_accum[slab][b][rem / 6][rem % 6] = 0.0;
    }
    if (tid < KK) {
        int i = tid >> 3, j = tid & 7;
        int y = 32 + 64 * i;
        int xc = 32 + 64 * j;
        const float* xb = x + (size_t)b * 3 * NPIX;
        float r  = xb[y * Ww + xc];
        float g  = xb[NPIX + y * Ww + xc];
        float bl = xb[2 * NPIX + y * Ww + xc];
        float fr = ratio_f();
        double* a = g_accum[0][b][tid];
        a[0] = (double)r;
        a[1] = (double)g;
        a[2] = (double)bl;
        a[3] = (double)__fmul_rn((float)y, fr);
        a[4] = (double)__fmul_rn((float)xc, fr);
        a[5] = 1.0;
    }
}

// ---------------------------------------------------------------------------
// assign pass it (R15 structure + PDL + native-packed pixel loads):
// PRE-SYNC (overlaps previous pass's tail via programmatic dependent launch):
//   tile ids, pixel LDG.128s (as ulonglong2 = native f32x2 pairs), sentinels.
// cudaGridDependencySynchronize() precedes any g_accum read (prior pass's
// atomics fully visible).  Centers computed in-prologue (fp32 div, JAX-style);
// segment sums atomically added to g_accum[it+1]; output recovered in
// finalize from slab SLIC_ITERS+1 (no labels, no weight pass).
// Exact spatial pruning; ascending-j compaction; +INF sentinel; fixed
// 8-candidate rounds; packed f32x2 distances (bit-identical to scalar).
// Warp-aggregated reduction: RGB shfl tree, cnt/Y/X exact ints via REDUX,
// lane 0 alone issues global f64 atomics.
// ---------------------------------------------------------------------------
__global__ __launch_bounds__(256, 3) void assign_kernel(const float* __restrict__ x,
                                                        int it) {
    __shared__ ulonglong2 s_pkA[64];          // {(-2c0,-2c0), (-2c1,-2c1)}
    __shared__ ulonglong2 s_pkB[64];          // {(-2c2,-2c2), (-2c3,-2c3)}
    __shared__ ulonglong2 s_pkC[64];          // {(-2c4,-2c4), (cc,cc) | +INF}
    __shared__ unsigned char s_jidx[64];
    __shared__ float s_smax[64];
    __shared__ unsigned int s_mask[2];
    __shared__ float s_T;

    int b   = blockIdx.y;
    int tid = threadIdx.x;
    int tileX = (blockIdx.x & 7) << 6;        // 8 x-tiles of 64
    int tileY = (blockIdx.x >> 3) << 5;       // 16 y-tiles of 32

    // ---- PRE-SYNC: pixel loads + sentinels (no g_accum access) ----
    int w    = tid >> 5;
    int lane = tid & 31;
    int patch_x = (lane & 7) | ((w & 1) << 3);   // 0..15
    int patch_y = (lane >> 3) | ((w >> 1) << 2); // 0..15
    int x0 = tileX + (patch_x << 2);
    int y0 = tileY + (patch_y << 1);
    const float* xr = x + (size_t)b * 3 * NPIX;
    const float* xg = xr + NPIX;
    const float* xb = xr + 2 * NPIX;
    // rows loaded directly as ulonglong2: .x = pixels(q0,q1), .y = (q2,q3),
    // natively usable as f32x2 operands (no PACK movs)
    ulonglong2 PRu[2], PGu[2], PBu[2];
#pragma unroll
    for (int r = 0; r < 2; r++) {
        PRu[r] = *(const ulonglong2*)(xr + (y0 + r) * Ww + x0);
        PGu[r] = *(const ulonglong2*)(xg + (y0 + r) * Ww + x0);
        PBu[r] = *(const ulonglong2*)(xb + (y0 + r) * Ww + x0);
    }
    if (tid < 64) {
        // sentinel: zero multipliers, +INF base -> d = +INF, never selected
        s_pkA[tid] = make_ulonglong2(0ull, 0ull);
        s_pkB[tid] = make_ulonglong2(0ull, 0ull);
        s_pkC[tid] = make_ulonglong2(0ull, 0x7f8000007f800000ull);
        s_jidx[tid] = 0;
        s_smax[tid] = 3.4e38f;
    }

    float fr = ratio_f();
    float byLo = __fmul_rn((float)tileY, fr);
    float byHi = __fmul_rn((float)(tileY + 31), fr);
    float bxLo = __fmul_rn((float)tileX, fr);
    float bxHi = __fmul_rn((float)(tileX + 63), fr);

    // ---- wait for previous pass's atomics to be fully visible ----
    cudaGridDependencySynchronize();

    float c0 = 0.f, c1 = 0.f, c2 = 0.f, c3 = 0.f, c4 = 0.f, smin = 0.f;
    if (tid < KK) {
        // centers from previous pass's sums (fused update, JAX-style fp32 div)
        const double* a = g_accum[it][b][tid];
        float fcnt = fmaxf((float)a[5], 1.0f);
        c0 = __fdiv_rn((float)a[0], fcnt);
        c1 = __fdiv_rn((float)a[1], fcnt);
        c2 = __fdiv_rn((float)a[2], fcnt);
        c3 = __fdiv_rn((float)a[3], fcnt);
        c4 = __fdiv_rn((float)a[4], fcnt);
        float dyo = fmaxf(fmaxf(byLo - c3, c3 - byHi), 0.0f);
        float dxo = fmaxf(fmaxf(bxLo - c4, c4 - bxHi), 0.0f);
        smin = dyo * dyo + dxo * dxo;
        float dyM = fmaxf(fabsf(c3 - byLo), fabsf(c3 - byHi));
        float dxM = fmaxf(fabsf(c4 - bxLo), fabsf(c4 - bxHi));
        s_smax[tid] = dyM * dyM + dxM * dxM;
    }
    __syncthreads();
    if (tid < 32) {                        // warp-parallel min reduction
        float v = fminf(s_smax[tid], s_smax[tid + 32]);
#pragma unroll
        for (int off = 16; off > 0; off >>= 1)
            v = fminf(v, __shfl_xor_sync(0xffffffffu, v, off));
        if (tid == 0) s_T = v + 3.0f + 1e-3f;  // color slack + fp pad
    }
    __syncthreads();
    bool keep = (tid < KK) && (smin <= s_T);
    unsigned int wm = __ballot_sync(0xffffffffu, keep);
    if (tid < 64 && (tid & 31) == 0) s_mask[tid >> 5] = wm;
    __syncthreads();
    unsigned int m0 = s_mask[0], m1 = s_mask[1];
    if (keep) {
        unsigned int mm = (tid < 32) ? m0 : m1;
        int base = (tid < 32) ? 0 : __popc(m0);
        int pos = base + __popc(mm & ((1u << (tid & 31)) - 1u));
        float cc = __fmul_rn(c0, c0);
        cc = __fmaf_rn(c1, c1, cc);
        cc = __fmaf_rn(c2, c2, cc);
        cc = __fmaf_rn(c3, c3, cc);
        cc = __fmaf_rn(c4, c4, cc);
        float n0 = __fmul_rn(-2.0f, c0), n1 = __fmul_rn(-2.0f, c1);
        float n2 = __fmul_rn(-2.0f, c2), n3 = __fmul_rn(-2.0f, c3);
        float n4 = __fmul_rn(-2.0f, c4);
        unsigned long long p0, p1, p2, p3, p4, p5;
        PACK_X2(p0, n0, n0); PACK_X2(p1, n1, n1);
        PACK_X2(p2, n2, n2); PACK_X2(p3, n3, n3);
        PACK_X2(p4, n4, n4); PACK_X2(p5, cc, cc);
        s_pkA[pos] = make_ulonglong2(p0, p1);
        s_pkB[pos] = make_ulonglong2(p2, p3);
        s_pkC[pos] = make_ulonglong2(p4, p5);
        s_jidx[pos] = (unsigned char)tid;
    }
    int C = __popc(m0) + __popc(m1);
    __syncthreads();

    float fxc[4], fy[2];
#pragma unroll
    for (int i = 0; i < 4; i++) fxc[i] = __fmul_rn((float)(x0 + i), fr);
#pragma unroll
    for (int i = 0; i < 2; i++) fy[i] = __fmul_rn((float)(y0 + i), fr);

    unsigned long long FX[2], FY[2];
    PACK_X2(FX[0], fxc[0], fxc[1]);
    PACK_X2(FX[1], fxc[2], fxc[3]);
    PACK_X2(FY[0], fy[0], fy[0]);
    PACK_X2(FY[1], fy[1], fy[1]);

    float dmin[8];
    int   lab[8];
#pragma unroll
    for (int p = 0; p < 8; p++) { dmin[p] = 3.4e38f; lab[p] = 0; }

    // fixed-trip unrolled rounds of 8 candidates (sentinel-padded, exact)
    int rounds = (C + 7) >> 3;             // 1-2 typically
    for (int rd = 0; rd < rounds; rd++) {
        int cbase = rd << 3;
#pragma unroll
        for (int i = 0; i < 8; i++) {
            int c = cbase + i;
            ulonglong2 pa = s_pkA[c];      // {n0n0, n1n1}
            ulonglong2 pb = s_pkB[c];      // {n2n2, n3n3}
            ulonglong2 pc = s_pkC[c];      // {n4n4, cccc}
            unsigned long long er0, er1;
            FMA_X2(er0, pb.y, FY[0], pc.y);
            FMA_X2(er1, pb.y, FY[1], pc.y);
#pragma unroll
            for (int r = 0; r < 2; r++) {
                unsigned long long er = (r == 0) ? er0 : er1;
#pragma unroll
                for (int h = 0; h < 2; h++) {
                    unsigned long long D;
                    unsigned long long pr = (h == 0) ? PRu[r].x : PRu[r].y;
                    unsigned long long pg = (h == 0) ? PGu[r].x : PGu[r].y;
                    unsigned long long pbv = (h == 0) ? PBu[r].x : PBu[r].y;
                    FMA_X2(D, pc.x, FX[h], er);
                    FMA_X2(D, pa.x, pr, D);
                    FMA_X2(D, pa.y, pg, D);
                    FMA_X2(D, pb.x, pbv, D);
                    float d0, d1;
                    UNPACK_X2(d0, d1, D);
                    int p = r * 4 + h * 2;
                    if (d0 < dmin[p])     { dmin[p] = d0;     lab[p] = c; }
                    if (d1 < dmin[p + 1]) { dmin[p + 1] = d1; lab[p + 1] = c; }
                }
            }
        }
    }

    // allow the next pass to begin its pre-sync phase
    cudaTriggerProgrammaticLaunchCompletion();

    // ---- warp-aggregated reduction ----
    unsigned int pmLo = 0, pmHi = 0;
#pragma unroll
    for (int p = 0; p < 8; p++) {
        int l = lab[p];
        if (l < 32) pmLo |= (1u << l);
        else        pmHi |= (1u << (l - 32));
    }
    pmLo = __reduce_or_sync(0xffffffffu, pmLo);
    pmHi = __reduce_or_sync(0xffffffffu, pmHi);

    double* gacc = (double*)g_accum[it + 1][b];
    double frd = (double)fr;

#pragma unroll 1
    for (int half = 0; half < 2; half++) {
        unsigned int m = (half == 0) ? pmLo : pmHi;
        int cofs = (half == 0) ? 0 : 32;
        while (m) {
            int c = __ffs(m) - 1;
            m &= (m - 1u);
            int slot = c + cofs;
            // predicated partials: floats for RGB, EXACT ints for cnt/Y/X
            float sR = 0.f, sG = 0.f, sB = 0.f;
            unsigned int icnt = 0, iy = 0, ix = 0;
#pragma unroll
            for (int p = 0; p < 8; p++) {
                int r = p >> 2, q = p & 3;
                bool hit = (lab[p] == slot);
                float mm = hit ? 1.0f : 0.0f;
                sR = __fmaf_rn(mm, ((const float*)&PRu[r])[q], sR);
                sG = __fmaf_rn(mm, ((const float*)&PGu[r])[q], sG);
                sB = __fmaf_rn(mm, ((const float*)&PBu[r])[q], sB);
                if (hit) { icnt += 1u; iy += (unsigned)(y0 + r); ix += (unsigned)(x0 + q); }
            }
            // R,G,B: shfl tree (deterministic); cnt/Y/X: hardware REDUX
#pragma unroll
            for (int off = 16; off > 0; off >>= 1) {
                sR += __shfl_xor_sync(0xffffffffu, sR, off);
                sG += __shfl_xor_sync(0xffffffffu, sG, off);
                sB += __shfl_xor_sync(0xffffffffu, sB, off);
            }
            icnt = __reduce_add_sync(0xffffffffu, icnt);
            iy   = __reduce_add_sync(0xffffffffu, iy);
            ix   = __reduce_add_sync(0xffffffffu, ix);
            if (lane == 0 && icnt != 0u) {
                int jj = s_jidx[slot];
                atomicAdd(&gacc[jj * 6 + 0], (double)sR);
                atomicAdd(&gacc[jj * 6 + 1], (double)sG);
                atomicAdd(&gacc[jj * 6 + 2], (double)sB);
                atomicAdd(&gacc[jj * 6 + 3], frd * (double)iy);
                atomicAdd(&gacc[jj * 6 + 4], frd * (double)ix);
                atomicAdd(&gacc[jj * 6 + 5], (double)icnt);
            }
        }
    }
}

// ---------------------------------------------------------------------------
// finalize: weighted mean = (1/N) * sum_k segsum_k / max(cnt_k, 1)
// (algebraic identity with the reference's per-pixel w=1/cnt weighting;
//  segment sums are f64 -> accuracy >= reference). One block per batch.
// ---------------------------------------------------------------------------
__global__ void finalize_kernel(float* __restrict__ out) {
    __shared__ double s_part[2][3];
    int b   = blockIdx.x;
    int tid = threadIdx.x;          // 64 threads
    double sr = 0.0, sg = 0.0, sb = 0.0;
    if (tid < KK) {
        const double* a = g_accum[SLIC_ITERS + 1][b][tid];
        float cntf = fmaxf((float)a[5], 1.0f);
        double inv = (double)__fdiv_rn(1.0f, cntf);   // JAX-style fp32 weight
        sr = a[0] * inv;
        sg = a[1] * inv;
        sb = a[2] * inv;
    }
#pragma unroll
    for (int off = 16; off > 0; off >>= 1) {
        sr += __shfl_xor_sync(0xffffffffu, sr, off);
        sg += __shfl_xor_sync(0xffffffffu, sg, off);
        sb += __shfl_xor_sync(0xffffffffu, sb, off);
    }
    if ((tid & 31) == 0) {
        s_part[tid >> 5][0] = sr;
        s_part[tid >> 5][1] = sg;
        s_part[tid >> 5][2] = sb;
    }
    __syncthreads();
    if (tid == 0) {
        float mr = (float)((s_part[0][0] + s_part[1][0]) / (double)NPIX);
        float mg = (float)((s_part[0][1] + s_part[1][1]) / (double)NPIX);
        float mb = (float)((s_part[0][2] + s_part[1][2]) / (double)NPIX);
        float drg = __fadd_rn(mr, -mg);
        float drb = __fadd_rn(mr, -mb);
        float dgb = __fadd_rn(mb, -mg);
        float Drg = __fmul_rn(drg, drg);
        float Drb = __fmul_rn(drb, drb);
        float Dgb = __fmul_rn(dgb, dgb);
        float t = __fadd_rn(__fadd_rn(__fmul_rn(Drg, Drg), __fmul_rn(Drb, Drb)),
                            __fmul_rn(Dgb, Dgb));
        out[b] = __fsqrt_rn(t);
    }
}

// ---------------------------------------------------------------------------
extern "C" void kernel_launch(void* const* d_in, const int* in_sizes, int n_in,
                              void* d_out, int out_size) {
    const float* x = (const float*)d_in[0];
    float* out = (float*)d_out;

    init_kernel<<<BB, 512>>>(x);

    // assign passes with programmatic dependent launch (pre-sync overlap)
    cudaLaunchConfig_t cfg = {};
    cfg.gridDim  = dim3(128, BB, 1);
    cfg.blockDim = dim3(256, 1, 1);
    cfg.dynamicSmemBytes = 0;
    cfg.stream = 0;
    cudaLaunchAttribute attrs[1];
    attrs[0].id = cudaLaunchAttributeProgrammaticStreamSerialization;
    attrs[0].val.programmaticStreamSerializationAllowed = 1;
    cfg.attrs = attrs;
    cfg.numAttrs = 1;
    for (int it = 0; it <= SLIC_ITERS; it++)          // 11 passes; last fills slab 11
        cudaLaunchKernelEx(&cfg, assign_kernel, x, it);

    finalize_kernel<<<BB, 64>>>(out);
}

// round 17
// speedup vs baseline: 1.7094x; 1.0399x over previous
#include <cuda_runtime.h>
#include <math.h>

#define Hh 512
#define Ww 512
#define NPIX (512*512)
#define KK 50
#define BB 16
#define SLIC_ITERS 10
#define NSLAB (SLIC_ITERS + 2)     // 12: slab it = input of assign pass it

// scratch (static device arrays; no dynamic allocation allowed)
__device__ double g_accum[NSLAB][BB][KK][6]; // [0..4]=feat sums, [5]=count

__device__ __forceinline__ float ratio_f() {
    return (float)(10.0 / sqrt((double)NPIX / (double)KK));
}

// packed f32x2 helpers (Blackwell sm_100+; per-half rounding == scalar FFMA)
#define FMA_X2(out, a, b, c) \
    asm("fma.rn.f32x2 %0, %1, %2, %3;" : "=l"(out) : "l"(a), "l"(b), "l"(c))
#define PACK_X2(out, lo, hi) \
    asm("mov.b64 %0, {%1, %2};" : "=l"(out) : "f"(lo), "f"(hi))
#define UNPACK_X2(lo, hi, in) \
    asm("mov.b64 {%0, %1}, %2;" : "=f"(lo), "=f"(hi) : "l"(in))
#define BAR64() asm volatile("bar.sync 1, 64;" ::: "memory")

// ---------------------------------------------------------------------------
// init: zero slabs 1..NSLAB-1, seed slab 0 with {feat, cnt=1} so that
// centers0 = feat/1 exactly (grid-initialized, first 50 of 8x8 grid)
// ---------------------------------------------------------------------------
__global__ void init_kernel(const float* __restrict__ x) {
    int b = blockIdx.x;
    int tid = threadIdx.x;
    for (int i = tid; i < (NSLAB - 1) * KK * 6; i += 512) {
        int slab = 1 + i / (KK * 6);
        int rem  = i % (KK * 6);
        g_accum[slab][b][rem / 6][rem % 6] = 0.0;
    }
    if (tid < KK) {
        int i = tid >> 3, j = tid & 7;
        int y = 32 + 64 * i;
        int xc = 32 + 64 * j;
        const float* xb = x + (size_t)b * 3 * NPIX;
        float r  = xb[y * Ww + xc];
        float g  = xb[NPIX + y * Ww + xc];
        float bl = xb[2 * NPIX + y * Ww + xc];
        float fr = ratio_f();
        double* a = g_accum[0][b][tid];
        a[0] = (double)r;
        a[1] = (double)g;
        a[2] = (double)bl;
        a[3] = (double)__fmul_rn((float)y, fr);
        a[4] = (double)__fmul_rn((float)xc, fr);
        a[5] = 1.0;
    }
}

// ---------------------------------------------------------------------------
// assign pass it (R16 + privatized prologue):
// PRE-SYNC (PDL overlap): tile ids, pixel LDG.128s (ulonglong2 = native f32x2
// pairs), sentinels.  After cudaGridDependencySynchronize(), candidate setup
// (centers, pruning threshold, ballot, compaction) is done ENTIRELY by warps
// 0-1, synchronized among themselves with named bar.sync(1,64); warps 2-7
// proceed to independent coordinate packing.  ONE full __syncthreads joins.
// Exact spatial pruning; ascending-j compaction; +INF sentinel; fixed
// 8-candidate rounds; packed f32x2 distances (bit-identical to scalar).
// Warp-aggregated reduction: RGB shfl tree, cnt/Y/X exact ints via REDUX,
// lane 0 alone issues global f64 atomics into slab it+1.
// ---------------------------------------------------------------------------
__global__ __launch_bounds__(256, 3) void assign_kernel(const float* __restrict__ x,
                                                        int it) {
    __shared__ ulonglong2 s_pkA[64];          // {(-2c0,-2c0), (-2c1,-2c1)}
    __shared__ ulonglong2 s_pkB[64];          // {(-2c2,-2c2), (-2c3,-2c3)}
    __shared__ ulonglong2 s_pkC[64];          // {(-2c4,-2c4), (cc,cc) | +INF}
    __shared__ unsigned char s_jidx[64];
    __shared__ float s_tmin[2];
    __shared__ unsigned int s_mask[2];
    __shared__ int s_C;

    int b   = blockIdx.y;
    int tid = threadIdx.x;
    int tileX = (blockIdx.x & 7) << 6;        // 8 x-tiles of 64
    int tileY = (blockIdx.x >> 3) << 5;       // 16 y-tiles of 32

    // ---- PRE-SYNC: pixel loads + sentinels (no g_accum access) ----
    int w    = tid >> 5;
    int lane = tid & 31;
    int patch_x = (lane & 7) | ((w & 1) << 3);   // 0..15
    int patch_y = (lane >> 3) | ((w >> 1) << 2); // 0..15
    int x0 = tileX + (patch_x << 2);
    int y0 = tileY + (patch_y << 1);
    const float* xr = x + (size_t)b * 3 * NPIX;
    const float* xg = xr + NPIX;
    const float* xb = xr + 2 * NPIX;
    ulonglong2 PRu[2], PGu[2], PBu[2];
#pragma unroll
    for (int r = 0; r < 2; r++) {
        PRu[r] = *(const ulonglong2*)(xr + (y0 + r) * Ww + x0);
        PGu[r] = *(const ulonglong2*)(xg + (y0 + r) * Ww + x0);
        PBu[r] = *(const ulonglong2*)(xb + (y0 + r) * Ww + x0);
    }
    if (tid < 64) {
        // sentinel: zero multipliers, +INF base -> d = +INF, never selected
        s_pkA[tid] = make_ulonglong2(0ull, 0ull);
        s_pkB[tid] = make_ulonglong2(0ull, 0ull);
        s_pkC[tid] = make_ulonglong2(0ull, 0x7f8000007f800000ull);
        s_jidx[tid] = 0;
    }

    float fr = ratio_f();

    // independent per-thread coordinate packing (overlaps candidate setup)
    float fxc[4], fy[2];
#pragma unroll
    for (int i = 0; i < 4; i++) fxc[i] = __fmul_rn((float)(x0 + i), fr);
#pragma unroll
    for (int i = 0; i < 2; i++) fy[i] = __fmul_rn((float)(y0 + i), fr);
    unsigned long long FX[2], FY[2];
    PACK_X2(FX[0], fxc[0], fxc[1]);
    PACK_X2(FX[1], fxc[2], fxc[3]);
    PACK_X2(FY[0], fy[0], fy[0]);
    PACK_X2(FY[1], fy[1], fy[1]);

    // ---- wait for previous pass's atomics to be fully visible ----
    cudaGridDependencySynchronize();

    // ---- candidate setup: PRIVATE to warps 0-1 (named barriers only) ----
    if (tid < 64) {
        float byLo = __fmul_rn((float)tileY, fr);
        float byHi = __fmul_rn((float)(tileY + 31), fr);
        float bxLo = __fmul_rn((float)tileX, fr);
        float bxHi = __fmul_rn((float)(tileX + 63), fr);

        float c0 = 0.f, c1 = 0.f, c2 = 0.f, c3 = 0.f, c4 = 0.f;
        float smin = 0.f, smax = 3.4e38f;
        if (tid < KK) {
            // centers from previous pass's sums (fused update, fp32 div)
            const double* a = g_accum[it][b][tid];
            float fcnt = fmaxf((float)a[5], 1.0f);
            c0 = __fdiv_rn((float)a[0], fcnt);
            c1 = __fdiv_rn((float)a[1], fcnt);
            c2 = __fdiv_rn((float)a[2], fcnt);
            c3 = __fdiv_rn((float)a[3], fcnt);
            c4 = __fdiv_rn((float)a[4], fcnt);
            float dyo = fmaxf(fmaxf(byLo - c3, c3 - byHi), 0.0f);
            float dxo = fmaxf(fmaxf(bxLo - c4, c4 - bxHi), 0.0f);
            smin = dyo * dyo + dxo * dxo;
            float dyM = fmaxf(fabsf(c3 - byLo), fabsf(c3 - byHi));
            float dxM = fmaxf(fabsf(c4 - bxLo), fabsf(c4 - bxHi));
            smax = dyM * dyM + dxM * dxM;
        }
        // per-warp min of smax, then 2-float exchange
        float v = smax;
#pragma unroll
        for (int off = 16; off > 0; off >>= 1)
            v = fminf(v, __shfl_xor_sync(0xffffffffu, v, off));
        if (lane == 0) s_tmin[w] = v;
        BAR64();
        float T = fminf(s_tmin[0], s_tmin[1]) + 3.0f + 1e-3f;  // color slack + pad
        bool keep = (tid < KK) && (smin <= T);
        unsigned int wm = __ballot_sync(0xffffffffu, keep);
        if (lane == 0) s_mask[w] = wm;
        BAR64();
        unsigned int m0 = s_mask[0], m1 = s_mask[1];
        if (keep) {
            unsigned int mm = (w == 0) ? m0 : m1;
            int base = (w == 0) ? 0 : __popc(m0);
            int pos = base + __popc(mm & ((1u << lane) - 1u));
            float cc = __fmul_rn(c0, c0);
            cc = __fmaf_rn(c1, c1, cc);
            cc = __fmaf_rn(c2, c2, cc);
            cc = __fmaf_rn(c3, c3, cc);
            cc = __fmaf_rn(c4, c4, cc);
            float n0 = __fmul_rn(-2.0f, c0), n1 = __fmul_rn(-2.0f, c1);
            float n2 = __fmul_rn(-2.0f, c2), n3 = __fmul_rn(-2.0f, c3);
            float n4 = __fmul_rn(-2.0f, c4);
            unsigned long long p0, p1, p2, p3, p4, p5;
            PACK_X2(p0, n0, n0); PACK_X2(p1, n1, n1);
            PACK_X2(p2, n2, n2); PACK_X2(p3, n3, n3);
            PACK_X2(p4, n4, n4); PACK_X2(p5, cc, cc);
            s_pkA[pos] = make_ulonglong2(p0, p1);
            s_pkB[pos] = make_ulonglong2(p2, p3);
            s_pkC[pos] = make_ulonglong2(p4, p5);
            s_jidx[pos] = (unsigned char)tid;
        }
        if (tid == 0) s_C = __popc(m0) + __popc(m1);
    }
    __syncthreads();                      // single full barrier
    int C = s_C;

    float dmin[8];
    int   lab[8];
#pragma unroll
    for (int p = 0; p < 8; p++) { dmin[p] = 3.4e38f; lab[p] = 0; }

    // fixed-trip unrolled rounds of 8 candidates (sentinel-padded, exact)
    int rounds = (C + 7) >> 3;             // 1-2 typically
    for (int rd = 0; rd < rounds; rd++) {
        int cbase = rd << 3;
#pragma unroll
        for (int i = 0; i < 8; i++) {
            int c = cbase + i;
            ulonglong2 pa = s_pkA[c];      // {n0n0, n1n1}
            ulonglong2 pb = s_pkB[c];      // {n2n2, n3n3}
            ulonglong2 pc = s_pkC[c];      // {n4n4, cccc}
            unsigned long long er0, er1;
            FMA_X2(er0, pb.y, FY[0], pc.y);
            FMA_X2(er1, pb.y, FY[1], pc.y);
#pragma unroll
            for (int r = 0; r < 2; r++) {
                unsigned long long er = (r == 0) ? er0 : er1;
#pragma unroll
                for (int h = 0; h < 2; h++) {
                    unsigned long long D;
                    unsigned long long pr = (h == 0) ? PRu[r].x : PRu[r].y;
                    unsigned long long pg = (h == 0) ? PGu[r].x : PGu[r].y;
                    unsigned long long pbv = (h == 0) ? PBu[r].x : PBu[r].y;
                    FMA_X2(D, pc.x, FX[h], er);
                    FMA_X2(D, pa.x, pr, D);
                    FMA_X2(D, pa.y, pg, D);
                    FMA_X2(D, pb.x, pbv, D);
                    float d0, d1;
                    UNPACK_X2(d0, d1, D);
                    int p = r * 4 + h * 2;
                    if (d0 < dmin[p])     { dmin[p] = d0;     lab[p] = c; }
                    if (d1 < dmin[p + 1]) { dmin[p + 1] = d1; lab[p + 1] = c; }
                }
            }
        }
    }

    // allow the next pass to begin its pre-sync phase
    cudaTriggerProgrammaticLaunchCompletion();

    // ---- warp-aggregated reduction ----
    unsigned int pmLo = 0, pmHi = 0;
#pragma unroll
    for (int p = 0; p < 8; p++) {
        int l = lab[p];
        if (l < 32) pmLo |= (1u << l);
        else        pmHi |= (1u << (l - 32));
    }
    pmLo = __reduce_or_sync(0xffffffffu, pmLo);
    pmHi = __reduce_or_sync(0xffffffffu, pmHi);

    double* gacc = (double*)g_accum[it + 1][b];
    double frd = (double)fr;

#pragma unroll 1
    for (int half = 0; half < 2; half++) {
        unsigned int m = (half == 0) ? pmLo : pmHi;
        int cofs = (half == 0) ? 0 : 32;
        while (m) {
            int c = __ffs(m) - 1;
            m &= (m - 1u);
            int slot = c + cofs;
            // predicated partials: floats for RGB, EXACT ints for cnt/Y/X
            float sR = 0.f, sG = 0.f, sB = 0.f;
            unsigned int icnt = 0, iy = 0, ix = 0;
#pragma unroll
            for (int p = 0; p < 8; p++) {
                int r = p >> 2, q = p & 3;
                bool hit = (lab[p] == slot);
                float mm = hit ? 1.0f : 0.0f;
                sR = __fmaf_rn(mm, ((const float*)&PRu[r])[q], sR);
                sG = __fmaf_rn(mm, ((const float*)&PGu[r])[q], sG);
                sB = __fmaf_rn(mm, ((const float*)&PBu[r])[q], sB);
                if (hit) { icnt += 1u; iy += (unsigned)(y0 + r); ix += (unsigned)(x0 + q); }
            }
            // R,G,B: shfl tree (deterministic); cnt/Y/X: hardware REDUX
#pragma unroll
            for (int off = 16; off > 0; off >>= 1) {
                sR += __shfl_xor_sync(0xffffffffu, sR, off);
                sG += __shfl_xor_sync(0xffffffffu, sG, off);
                sB += __shfl_xor_sync(0xffffffffu, sB, off);
            }
            icnt = __reduce_add_sync(0xffffffffu, icnt);
            iy   = __reduce_add_sync(0xffffffffu, iy);
            ix   = __reduce_add_sync(0xffffffffu, ix);
            if (lane == 0 && icnt != 0u) {
                int jj = s_jidx[slot];
                atomicAdd(&gacc[jj * 6 + 0], (double)sR);
                atomicAdd(&gacc[jj * 6 + 1], (double)sG);
                atomicAdd(&gacc[jj * 6 + 2], (double)sB);
                atomicAdd(&gacc[jj * 6 + 3], frd * (double)iy);
                atomicAdd(&gacc[jj * 6 + 4], frd * (double)ix);
                atomicAdd(&gacc[jj * 6 + 5], (double)icnt);
            }
        }
    }
}

// ---------------------------------------------------------------------------
// finalize: weighted mean = (1/N) * sum_k segsum_k / max(cnt_k, 1)
// (algebraic identity with the reference's per-pixel w=1/cnt weighting;
//  segment sums are f64 -> accuracy >= reference). One block per batch.
// ---------------------------------------------------------------------------
__global__ void finalize_kernel(float* __restrict__ out) {
    __shared__ double s_part[2][3];
    int b   = blockIdx.x;
    int tid = threadIdx.x;          // 64 threads
    double sr = 0.0, sg = 0.0, sb = 0.0;
    if (tid < KK) {
        const double* a = g_accum[SLIC_ITERS + 1][b][tid];
        float cntf = fmaxf((float)a[5], 1.0f);
        double inv = (double)__fdiv_rn(1.0f, cntf);   // JAX-style fp32 weight
        sr = a[0] * inv;
        sg = a[1] * inv;
        sb = a[2] * inv;
    }
#pragma unroll
    for (int off = 16; off > 0; off >>= 1) {
        sr += __shfl_xor_sync(0xffffffffu, sr, off);
        sg += __shfl_xor_sync(0xffffffffu, sg, off);
        sb += __shfl_xor_sync(0xffffffffu, sb, off);
    }
    if ((tid & 31) == 0) {
        s_part[tid >> 5][0] = sr;
        s_part[tid >> 5][1] = sg;
        s_part[tid >> 5][2] = sb;
    }
    __syncthreads();
    if (tid == 0) {
        float mr = (float)((s_part[0][0] + s_part[1][0]) / (double)NPIX);
        float mg = (float)((s_part[0][1] + s_part[1][1]) / (double)NPIX);
        float mb = (float)((s_part[0][2] + s_part[1][2]) / (double)NPIX);
        float drg = __fadd_rn(mr, -mg);
        float drb = __fadd_rn(mr, -mb);
        float dgb = __fadd_rn(mb, -mg);
        float Drg = __fmul_rn(drg, drg);
        float Drb = __fmul_rn(drb, drb);
        float Dgb = __fmul_rn(dgb, dgb);
        float t = __fadd_rn(__fadd_rn(__fmul_rn(Drg, Drg), __fmul_rn(Drb, Drb)),
                            __fmul_rn(Dgb, Dgb));
        out[b] = __fsqrt_rn(t);
    }
}

// ---------------------------------------------------------------------------
extern "C" void kernel_launch(void* const* d_in, const int* in_sizes, int n_in,
                              void* d_out, int out_size) {
    const float* x = (const float*)d_in[0];
    float* out = (float*)d_out;

    init_kernel<<<BB, 512>>>(x);

    // assign passes with programmatic dependent launch (pre-sync overlap)
    cudaLaunchConfig_t cfg = {};
    cfg.gridDim  = dim3(128, BB, 1);
    cfg.blockDim = dim3(256, 1, 1);
    cfg.dynamicSmemBytes = 0;
    cfg.stream = 0;
    cudaLaunchAttribute attrs[1];
    attrs[0].id = cudaLaunchAttributeProgrammaticStreamSerialization;
    attrs[0].val.programmaticStreamSerializationAllowed = 1;
    cfg.attrs = attrs;
    cfg.numAttrs = 1;
    for (int it = 0; it <= SLIC_ITERS; it++)          // 11 passes; last fills slab 11
        cudaLaunchKernelEx(&cfg, assign_kernel, x, it);

    finalize_kernel<<<BB, 64>>>(out);
}